// round 9
// baseline (speedup 1.0000x reference)
#include <cuda_runtime.h>
#include <cstdint>

// Dice loss: pred (8,62,512,512) f32 logits, target (8,512,512) i32 -> scalar f32.
// Single HBM pass over pred (520MB), HBM-bound target ~66us.
// R8 changes vs R5 (94.7us):
//  - inter+count packed into ONE shared atomic per pixel (K=512) -> halves ATOMS/LSU load
//  - no init kernel: per-CTA partial slots written unconditionally (graph-replay safe)
//  - parallel finish kernel (16 lanes x 62 classes)

#define NC      62
#define HWV     (512 * 512)
#define NPIX    (8 * 512 * 512)
#define IGNORE  255
#define NBLK    304            // 2 CTAs/SM x 152 SMs
#define KP      512.0f
#define KPINV   (1.0f / 512.0f)

__device__ float g_pred_part[NC * NBLK];   // [c][b] per-CTA sum of softmax probs
__device__ float g_ic_part[NC * NBLK];     // [c][b] packed: KP*count + inter

__global__ __launch_bounds__(256, 2)
void dice_main(const float* __restrict__ pred, const int* __restrict__ target) {
    __shared__ float s_ic[NC];    // packed inter+count, per class
    __shared__ float s1[8][NC];   // per-warp staging for acc1 reduction

    for (int i = threadIdx.x; i < NC; i += 256) s_ic[i] = 0.f;
    __syncthreads();

    float acc1[NC];               // per-class sum of softmax probs (valid pixels)
#pragma unroll
    for (int c = 0; c < NC; ++c) acc1[c] = 0.f;

    const float L2E = 1.4426950408889634f;
    const int stride = gridDim.x * blockDim.x;

    for (int p = blockIdx.x * blockDim.x + threadIdx.x; p < NPIX; p += stride) {
        const int n  = p >> 18;
        const int hw = p & (HWV - 1);
        const float* base = pred + (long long)n * (NC * HWV) + hw;

        const int t = __ldg(target + p);
        const bool valid = (t != IGNORE);

        uint32_t epk[NC / 2];     // 31 packed bf16x2 exp values
        float d0 = 0.f, d1 = 0.f;
        float et = 0.f;

#pragma unroll
        for (int c = 0; c < NC; c += 2) {
            const float xa = __ldg(base + (size_t)c * HWV);
            const float xb = __ldg(base + (size_t)(c + 1) * HWV);
            float ea, eb;
            asm("ex2.approx.ftz.f32 %0, %1;" : "=f"(ea) : "f"(xa * L2E));
            asm("ex2.approx.ftz.f32 %0, %1;" : "=f"(eb) : "f"(xb * L2E));
            d0 += ea;
            d1 += eb;
            et = (c     == t) ? ea : et;
            et = (c + 1 == t) ? eb : et;
            uint32_t pk;
            asm("cvt.rn.bf16x2.f32 %0, %1, %2;" : "=r"(pk) : "f"(eb), "f"(ea)); // hi=eb, lo=ea
            epk[c >> 1] = pk;
        }

        float inv;
        asm("rcp.approx.ftz.f32 %0, %1;" : "=f"(inv) : "f"(d0 + d1));
        const float invv = valid ? inv : 0.f;

        // one packed shared atomic per valid pixel: KP*1 + prob_at_target
        if (valid) atomicAdd(&s_ic[t], fmaf(et, inv, KP));

#pragma unroll
        for (int c = 0; c < NC; c += 2) {
            const uint32_t pk = epk[c >> 1];
            const float ea = __uint_as_float(pk << 16);
            const float eb = __uint_as_float(pk & 0xffff0000u);
            acc1[c]     = fmaf(ea, invv, acc1[c]);
            acc1[c + 1] = fmaf(eb, invv, acc1[c + 1]);
        }
    }

    // Reduce acc1: warp butterfly per class -> shared -> per-CTA global slot.
    const int lane = threadIdx.x & 31;
    const int w    = threadIdx.x >> 5;
#pragma unroll
    for (int c = 0; c < NC; ++c) {
        float v = acc1[c];
#pragma unroll
        for (int s = 16; s; s >>= 1) v += __shfl_xor_sync(0xffffffffu, v, s);
        if (lane == 0) s1[w][c] = v;
    }
    __syncthreads();

    for (int c = threadIdx.x; c < NC; c += 256) {
        float a = 0.f;
#pragma unroll
        for (int ww = 0; ww < 8; ++ww) a += s1[ww][c];
        g_pred_part[c * NBLK + blockIdx.x] = a;
        g_ic_part[c * NBLK + blockIdx.x]   = s_ic[c];
    }
}

// block (16, 62): 16 lanes per class reduce the 304 per-CTA partials.
__global__ void dice_finish(float* __restrict__ out) {
    __shared__ float sh_ds[NC];
    __shared__ float sh_nv[NC];
    const int i = threadIdx.x;   // 0..15
    const int c = threadIdx.y;   // 0..61

    float sp = 0.f, si = 0.f, sc = 0.f;
#pragma unroll 4
    for (int b = i; b < NBLK; b += 16) {
        sp += g_pred_part[c * NBLK + b];
        const float v  = g_ic_part[c * NBLK + b];
        const float cf = floorf(v * KPINV);
        si = fmaf(-KP, cf, v) + si;   // inter part
        sc += cf;                      // count part
    }
#pragma unroll
    for (int s = 8; s; s >>= 1) {
        sp += __shfl_xor_sync(0xffffffffu, sp, s);
        si += __shfl_xor_sync(0xffffffffu, si, s);
        sc += __shfl_xor_sync(0xffffffffu, sc, s);
    }
    if (i == 0) {
        const float u    = sp + sc;
        const float dice = (2.f * si + 1e-6f) / (u + 1e-6f);
        sh_ds[c] = (u > 0.f) ? dice : 0.f;
        sh_nv[c] = (u > 0.f) ? 1.f : 0.f;
    }
    __syncthreads();
    if (i == 0 && c == 0) {
        float ds = 0.f, nv = 0.f;
#pragma unroll
        for (int k = 0; k < NC; ++k) { ds += sh_ds[k]; nv += sh_nv[k]; }
        const float md = (nv > 0.f) ? (ds / fmaxf(nv, 1.f)) : 1.f;
        out[0] = 1.f - md;
    }
}

extern "C" void kernel_launch(void* const* d_in, const int* in_sizes, int n_in,
                              void* d_out, int out_size) {
    const float* pred   = (const float*)d_in[0];
    const int*   target = (const int*)d_in[1];
    float*       out    = (float*)d_out;

    dice_main<<<NBLK, 256>>>(pred, target);
    dice_finish<<<1, dim3(16, NC)>>>(out);
}

// round 10
// speedup vs baseline: 1.0078x; 1.0078x over previous
#include <cuda_runtime.h>
#include <cstdint>

// Dice loss: pred (8,62,512,512) f32 logits, target (8,512,512) i32 -> scalar f32.
// Single HBM pass over pred (520MB); single kernel launch.
// R9 changes vs R8 (94.7us, of which dice_finish was 8.26us):
//  - finish fused into dice_main via threadfence-reduction (last CTA reduces partials)
//  - __ldcs streaming loads for pred (zero reuse)

#define NC      62
#define HWV     (512 * 512)
#define NPIX    (8 * 512 * 512)
#define IGNORE  255
#define NBLK    304            // 2 CTAs/SM x 152 SMs
#define KP      512.0f
#define KPINV   (1.0f / 512.0f)

__device__ float g_pred_part[NC * NBLK];   // [c][b] per-CTA sum of softmax probs
__device__ float g_ic_part[NC * NBLK];     // [c][b] packed: KP*count + inter
__device__ unsigned g_ticket;              // zero-init; last CTA resets to 0

__global__ __launch_bounds__(256, 2)
void dice_main(const float* __restrict__ pred, const int* __restrict__ target,
               float* __restrict__ out) {
    __shared__ float s_ic[NC];    // packed inter+count, per class
    __shared__ float s1[8][NC];   // per-warp staging for acc1 reduction
    __shared__ float sh_ds[NC];
    __shared__ float sh_nv[NC];
    __shared__ bool  s_last;

    for (int i = threadIdx.x; i < NC; i += 256) s_ic[i] = 0.f;
    __syncthreads();

    float acc1[NC];               // per-class sum of softmax probs (valid pixels)
#pragma unroll
    for (int c = 0; c < NC; ++c) acc1[c] = 0.f;

    const float L2E = 1.4426950408889634f;
    const int stride = gridDim.x * blockDim.x;

    for (int p = blockIdx.x * blockDim.x + threadIdx.x; p < NPIX; p += stride) {
        const int n  = p >> 18;
        const int hw = p & (HWV - 1);
        const float* base = pred + (long long)n * (NC * HWV) + hw;

        const int t = __ldg(target + p);
        const bool valid = (t != IGNORE);

        uint32_t epk[NC / 2];     // 31 packed bf16x2 exp values
        float d0 = 0.f, d1 = 0.f;
        float et = 0.f;

#pragma unroll
        for (int c = 0; c < NC; c += 2) {
            const float xa = __ldcs(base + (size_t)c * HWV);
            const float xb = __ldcs(base + (size_t)(c + 1) * HWV);
            float ea, eb;
            asm("ex2.approx.ftz.f32 %0, %1;" : "=f"(ea) : "f"(xa * L2E));
            asm("ex2.approx.ftz.f32 %0, %1;" : "=f"(eb) : "f"(xb * L2E));
            d0 += ea;
            d1 += eb;
            et = (c     == t) ? ea : et;
            et = (c + 1 == t) ? eb : et;
            uint32_t pk;
            asm("cvt.rn.bf16x2.f32 %0, %1, %2;" : "=r"(pk) : "f"(eb), "f"(ea)); // hi=eb, lo=ea
            epk[c >> 1] = pk;
        }

        float inv;
        asm("rcp.approx.ftz.f32 %0, %1;" : "=f"(inv) : "f"(d0 + d1));
        const float invv = valid ? inv : 0.f;

        // one packed shared atomic per valid pixel: KP*1 + prob_at_target
        if (valid) atomicAdd(&s_ic[t], fmaf(et, inv, KP));

#pragma unroll
        for (int c = 0; c < NC; c += 2) {
            const uint32_t pk = epk[c >> 1];
            const float ea = __uint_as_float(pk << 16);
            const float eb = __uint_as_float(pk & 0xffff0000u);
            acc1[c]     = fmaf(ea, invv, acc1[c]);
            acc1[c + 1] = fmaf(eb, invv, acc1[c + 1]);
        }
    }

    // Reduce acc1: warp butterfly per class -> shared -> per-CTA global slot.
    const int lane = threadIdx.x & 31;
    const int w    = threadIdx.x >> 5;
#pragma unroll
    for (int c = 0; c < NC; ++c) {
        float v = acc1[c];
#pragma unroll
        for (int s = 16; s; s >>= 1) v += __shfl_xor_sync(0xffffffffu, v, s);
        if (lane == 0) s1[w][c] = v;
    }
    __syncthreads();

    for (int c = threadIdx.x; c < NC; c += 256) {
        float a = 0.f;
#pragma unroll
        for (int ww = 0; ww < 8; ++ww) a += s1[ww][c];
        g_pred_part[c * NBLK + blockIdx.x] = a;
        g_ic_part[c * NBLK + blockIdx.x]   = s_ic[c];
    }

    // ---- threadfence reduction: last CTA to arrive does the final reduce ----
    __threadfence();
    if (threadIdx.x == 0) {
        const unsigned tk = atomicAdd(&g_ticket, 1u);
        s_last = (tk == NBLK - 1);
    }
    __syncthreads();
    if (!s_last) return;

    __threadfence();  // acquire side: partials from all CTAs now visible

    // 8 warps x 32 lanes; warp w handles classes c = w, w+8, ... (L2-resident reads)
    for (int c = w; c < NC; c += 8) {
        float sp = 0.f, si = 0.f, sc = 0.f;
#pragma unroll
        for (int b = lane; b < NBLK; b += 32) {
            sp += g_pred_part[c * NBLK + b];
            const float v  = g_ic_part[c * NBLK + b];
            const float cf = floorf(v * KPINV);
            si = fmaf(-KP, cf, v) + si;   // inter part
            sc += cf;                      // count part
        }
#pragma unroll
        for (int s = 16; s; s >>= 1) {
            sp += __shfl_xor_sync(0xffffffffu, sp, s);
            si += __shfl_xor_sync(0xffffffffu, si, s);
            sc += __shfl_xor_sync(0xffffffffu, sc, s);
        }
        if (lane == 0) {
            const float u    = sp + sc;
            const float dice = (2.f * si + 1e-6f) / (u + 1e-6f);
            sh_ds[c] = (u > 0.f) ? dice : 0.f;
            sh_nv[c] = (u > 0.f) ? 1.f : 0.f;
        }
    }
    __syncthreads();
    if (threadIdx.x == 0) {
        float ds = 0.f, nv = 0.f;
#pragma unroll
        for (int k = 0; k < NC; ++k) { ds += sh_ds[k]; nv += sh_nv[k]; }
        const float md = (nv > 0.f) ? (ds / fmaxf(nv, 1.f)) : 1.f;
        out[0] = 1.f - md;
        g_ticket = 0;   // reset for next graph replay (only this CTA touches it now)
    }
}

extern "C" void kernel_launch(void* const* d_in, const int* in_sizes, int n_in,
                              void* d_out, int out_size) {
    const float* pred   = (const float*)d_in[0];
    const int*   target = (const int*)d_in[1];
    float*       out    = (float*)d_out;

    dice_main<<<NBLK, 256>>>(pred, target, out);
}